// round 1
// baseline (speedup 1.0000x reference)
#include <cuda_runtime.h>
#include <math.h>

#define DEPTH   5
#define HID     128
#define CODEL   400
#define NFREQ   9
#define NSTACK  6      // DEPTH+1
#define TPB     64     // points per block
#define THREADS 256    // 8 warps
#define PPW     8      // points per warp
#define WPITCH  129    // smem pitch for weight tile (conflict-free)
#define MAXB    16

// Scratch (no cudaMalloc allowed): normalization coefs + per-batch code vectors
__device__ float g_norm[5][6];
__device__ float g_code[DEPTH * MAXB * HID];

// ---------------------------------------------------------------------------
// 1-thread init: Y_l^m normalization coefficients in double precision.
// coef(m,s) for l = m+s:  K = sqrt((2l+1)/(4pi) * (l-m)!/(l+m)!)
//   m==0 : K
//   m>0  : (-1)^m * sqrt(2) * K      (sign from the real-harmonic combos)
// ---------------------------------------------------------------------------
__global__ void init_norm_kernel() {
    if (threadIdx.x == 0) {
        for (int m = 0; m <= 4; m++) {
            for (int s = 0; s <= 5; s++) {
                int l = m + s;
                double f = 1.0;
                for (int q = l - m + 1; q <= l + m; q++) f *= (double)q;
                double K = sqrt((2.0 * l + 1.0) / (4.0 * M_PI) / f);
                double coef = (m == 0) ? K : ((m & 1) ? -sqrt(2.0) * K : sqrt(2.0) * K);
                g_norm[m][s] = (float)coef;
            }
        }
    }
}

// ---------------------------------------------------------------------------
// Per-(layer,batch) code vector: g_code[i][b][h] =
//     bfwd[i][h] + bcode[i][h] + sum_c Wcode[i][h][c] * a[b][c]
// This hoists the CODE-length dot out of the per-point loop entirely.
// ---------------------------------------------------------------------------
__global__ void code_kernel(const float* __restrict__ a,
                            const float* __restrict__ Wcode,
                            const float* __restrict__ bcode,
                            const float* __restrict__ bfwd,
                            int B) {
    int i = blockIdx.x;
    int b = blockIdx.y;
    int h = threadIdx.x;
    float acc = bfwd[i * HID + h] + bcode[i * HID + h];
    const float* wr = Wcode + ((long)i * HID + h) * CODEL;
    const float* av = a + (long)b * CODEL;
    #pragma unroll 4
    for (int c = 0; c < CODEL; c++) acc = fmaf(wr[c], av[c], acc);
    g_code[(i * B + b) * HID + h] = acc;
}

// ---------------------------------------------------------------------------
// Main fused kernel. Block = 256 threads = 8 warps; TPB=64 points per block,
// PPW=8 points per warp. Lane l owns channels {l, l+32, l+64, l+96}.
// z[point][128] lives in SMEM (reads are warp-broadcast LDS -> conflict free).
// Wfwd[i] staged per layer into SMEM with pitch 129 (conflict-free).
// ---------------------------------------------------------------------------
__global__ void __launch_bounds__(THREADS)
main_kernel(const float* __restrict__ x,
            const float* __restrict__ Wftr,
            const float* __restrict__ bftr,
            const float* __restrict__ Wfwd,
            const float* __restrict__ Wout,
            const float* __restrict__ bout,
            float* __restrict__ out,
            int N, int B) {
    extern __shared__ float sm[];
    float* Wsh   = sm;                                   // HID * WPITCH
    float* zsh   = Wsh   + HID * WPITCH;                 // TPB * HID
    float* ysh   = zsh   + TPB * HID;                    // NSTACK*TPB*NFREQ
    float* Wftrs = ysh   + NSTACK * TPB * NFREQ;         // NSTACK*HID*NFREQ
    float* bftrs = Wftrs + NSTACK * HID * NFREQ;         // NSTACK*HID

    const int t    = threadIdx.x;
    const int warp = t >> 5;
    const int lane = t & 31;
    const long ptBase = (long)blockIdx.x * TPB;
    const int b  = (int)(ptBase / N);
    const int n0 = (int)(ptBase % N);

    // --- stage small filter weights ---
    for (int idx = t; idx < NSTACK * HID * NFREQ; idx += THREADS) Wftrs[idx] = Wftr[idx];
    for (int idx = t; idx < NSTACK * HID; idx += THREADS)         bftrs[idx] = bftr[idx];

    // --- spherical-harmonic features: thread p<64 computes one point ---
    if (t < TPB) {
        const float* xp = x + ((long)b * N + n0 + t) * 2;
        float theta = xp[0];
        float phi   = xp[1];
        float c  = cosf(phi);
        float s2 = sqrtf(fmaxf(1.0f - c * c, 0.0f));
        float ct = cosf(theta), st = sinf(theta);
        float cmv = 1.0f, smv = 0.0f;   // cos(m*theta), sin(m*theta)
        float pmm = 1.0f;               // P_m^m with Condon-Shortley phase
        for (int m = 0; m <= 4; m++) {
            if (m > 0) {
                pmm *= -(2.0f * m - 1.0f) * s2;
                float cn = cmv * ct - smv * st;
                float sn = smv * ct + cmv * st;
                cmv = cn; smv = sn;
            }
            float Pm2 = pmm;                           // P_m^m
            float Pm1 = c * (2.0f * m + 1.0f) * pmm;   // P_{m+1}^m
            for (int s = 0; s <= 5; s++) {
                float P;
                if (s == 0)      P = Pm2;
                else if (s == 1) P = Pm1;
                else {
                    int l = m + s;
                    float Pl = ((2.0f * l - 1.0f) * c * Pm1
                                - (float)(l + m - 1) * Pm2) / (float)(l - m);
                    Pm2 = Pm1; Pm1 = Pl; P = Pl;
                }
                float base = g_norm[m][s] * P;
                float* yrow = ysh + (s * TPB + t) * NFREQ;
                if (m == 0) {
                    yrow[4] = base;
                } else {
                    yrow[4 + m] = base * cmv;   // cos branch (m > 0)
                    yrow[4 - m] = base * smv;   // sin branch (m < 0)
                }
            }
        }
    }
    __syncthreads();

    // --- z0 = Wftr[0] @ y0 + bftr[0] ---
    float acc[PPW][4];
    {
        float f0[4];
        #pragma unroll
        for (int j = 0; j < 4; j++) f0[j] = bftrs[lane + 32 * j];
        #pragma unroll
        for (int p = 0; p < PPW; p++) {
            float F0 = f0[0], F1 = f0[1], F2 = f0[2], F3 = f0[3];
            const float* yrow = ysh + (0 * TPB + warp * PPW + p) * NFREQ;
            #pragma unroll
            for (int f = 0; f < NFREQ; f++) {
                float yv = yrow[f];
                F0 = fmaf(Wftrs[(lane      ) * NFREQ + f], yv, F0);
                F1 = fmaf(Wftrs[(lane + 32 ) * NFREQ + f], yv, F1);
                F2 = fmaf(Wftrs[(lane + 64 ) * NFREQ + f], yv, F2);
                F3 = fmaf(Wftrs[(lane + 96 ) * NFREQ + f], yv, F3);
            }
            float* zr = zsh + (warp * PPW + p) * HID;
            zr[lane      ] = F0;
            zr[lane + 32 ] = F1;
            zr[lane + 64 ] = F2;
            zr[lane + 96 ] = F3;
        }
    }
    __syncwarp();

    // --- layers ---
    for (int i = 0; i < DEPTH; i++) {
        // stage Wfwd[i] into smem (pitch 129: conflict-free store + read)
        __syncthreads();
        const float* Wg = Wfwd + (long)i * HID * HID;
        for (int idx = t; idx < HID * HID; idx += THREADS) {
            int g = idx >> 7, k = idx & 127;
            Wsh[g * WPITCH + k] = Wg[idx];
        }
        __syncthreads();

        // init acc with precomputed code vector (bfwd+bcode+Wcode@a)
        float cj0 = g_code[(i * B + b) * HID + lane      ];
        float cj1 = g_code[(i * B + b) * HID + lane + 32 ];
        float cj2 = g_code[(i * B + b) * HID + lane + 64 ];
        float cj3 = g_code[(i * B + b) * HID + lane + 96 ];
        #pragma unroll
        for (int p = 0; p < PPW; p++) {
            acc[p][0] = cj0; acc[p][1] = cj1; acc[p][2] = cj2; acc[p][3] = cj3;
        }

        // matvec: acc[p][j] += sum_k Wfwd[g_j][k] * z[p][k]
        const float* zr = zsh + (warp * PPW) * HID;
        const float* w0p = Wsh + (lane      ) * WPITCH;
        const float* w1p = Wsh + (lane + 32 ) * WPITCH;
        const float* w2p = Wsh + (lane + 64 ) * WPITCH;
        const float* w3p = Wsh + (lane + 96 ) * WPITCH;
        #pragma unroll 4
        for (int k = 0; k < HID; k++) {
            float w0 = w0p[k], w1 = w1p[k], w2 = w2p[k], w3 = w3p[k];
            #pragma unroll
            for (int p = 0; p < PPW; p++) {
                float zv = zr[p * HID + k];       // warp broadcast
                acc[p][0] = fmaf(w0, zv, acc[p][0]);
                acc[p][1] = fmaf(w1, zv, acc[p][1]);
                acc[p][2] = fmaf(w2, zv, acc[p][2]);
                acc[p][3] = fmaf(w3, zv, acc[p][3]);
            }
        }

        // modulate by filter stack (i+1)
        const int s = i + 1;
        float bf0 = bftrs[s * HID + lane      ];
        float bf1 = bftrs[s * HID + lane + 32 ];
        float bf2 = bftrs[s * HID + lane + 64 ];
        float bf3 = bftrs[s * HID + lane + 96 ];
        #pragma unroll
        for (int p = 0; p < PPW; p++) {
            float F0 = bf0, F1 = bf1, F2 = bf2, F3 = bf3;
            const float* yrow = ysh + (s * TPB + warp * PPW + p) * NFREQ;
            #pragma unroll
            for (int f = 0; f < NFREQ; f++) {
                float yv = yrow[f];
                F0 = fmaf(Wftrs[(s * HID + lane      ) * NFREQ + f], yv, F0);
                F1 = fmaf(Wftrs[(s * HID + lane + 32 ) * NFREQ + f], yv, F1);
                F2 = fmaf(Wftrs[(s * HID + lane + 64 ) * NFREQ + f], yv, F2);
                F3 = fmaf(Wftrs[(s * HID + lane + 96 ) * NFREQ + f], yv, F3);
            }
            acc[p][0] *= F0; acc[p][1] *= F1; acc[p][2] *= F2; acc[p][3] *= F3;
        }

        if (i < DEPTH - 1) {
            __syncwarp();   // all lanes done reading old z
            #pragma unroll
            for (int p = 0; p < PPW; p++) {
                float* zw = zsh + (warp * PPW + p) * HID;
                zw[lane      ] = acc[p][0];
                zw[lane + 32 ] = acc[p][1];
                zw[lane + 64 ] = acc[p][2];
                zw[lane + 96 ] = acc[p][3];
            }
            __syncwarp();
        }
    }

    // --- out = z . Wout + bout ---
    float wo0 = Wout[lane      ];
    float wo1 = Wout[lane + 32 ];
    float wo2 = Wout[lane + 64 ];
    float wo3 = Wout[lane + 96 ];
    float bo  = *bout;
    #pragma unroll
    for (int p = 0; p < PPW; p++) {
        float v = acc[p][0] * wo0 + acc[p][1] * wo1
                + acc[p][2] * wo2 + acc[p][3] * wo3;
        #pragma unroll
        for (int o = 16; o > 0; o >>= 1) v += __shfl_xor_sync(0xffffffffu, v, o);
        if (lane == 0) out[(long)b * N + n0 + warp * PPW + p] = v + bo;
    }
}

// ---------------------------------------------------------------------------
extern "C" void kernel_launch(void* const* d_in, const int* in_sizes, int n_in,
                              void* d_out, int out_size) {
    const float* x     = (const float*)d_in[0];
    const float* a     = (const float*)d_in[1];
    const float* Wftr  = (const float*)d_in[2];
    const float* bftr  = (const float*)d_in[3];
    const float* Wfwd  = (const float*)d_in[4];
    const float* bfwd  = (const float*)d_in[5];
    const float* Wcode = (const float*)d_in[6];
    const float* bcode = (const float*)d_in[7];
    const float* Wout  = (const float*)d_in[8];
    const float* bout  = (const float*)d_in[9];
    float* out = (float*)d_out;

    int  B  = in_sizes[1] / CODEL;          // a: [B,1,CODE]
    long BN = (long)in_sizes[0] / 2;        // x: [B,N,2]
    int  N  = (int)(BN / B);

    init_norm_kernel<<<1, 32>>>();
    dim3 gcode(DEPTH, B);
    code_kernel<<<gcode, HID>>>(a, Wcode, bcode, bfwd, B);

    size_t smem = (size_t)(HID * WPITCH + TPB * HID + NSTACK * TPB * NFREQ
                           + NSTACK * HID * NFREQ + NSTACK * HID) * sizeof(float);
    cudaFuncSetAttribute(main_kernel, cudaFuncAttributeMaxDynamicSharedMemorySize,
                         (int)smem);
    int blocks = (int)(BN / TPB);
    main_kernel<<<blocks, THREADS, smem>>>(x, Wftr, bftr, Wfwd, Wout, bout, out, N, B);

    // reference returns (out, x): append a copy of x after out
    if ((long)out_size >= BN * 3) {
        cudaMemcpyAsync(out + BN, x, (size_t)BN * 2 * sizeof(float),
                        cudaMemcpyDeviceToDevice, 0);
    }
}

// round 3
// speedup vs baseline: 2.9787x; 2.9787x over previous
#include <cuda_runtime.h>
#include <cuda_bf16.h>
#include <math.h>
#include <stdint.h>

#define DEPTH   5
#define HID     128
#define CODEL   400
#define MAXB    16
#define TILE    128
#define NTHREADS 256

// ---- SMEM byte map ----
#define SM_ZH    0         // z hi plane   128x256B (swizzled)
#define SM_ZL    32768
#define SM_WH    65536     // Wfwd hi stage
#define SM_WL    98304
#define SM_FH    131072    // Wftr hi, 6 stacks x 128ch x 32B
#define SM_FL    155648
#define SM_YH    180224    // Y hi, 128pt x 32B
#define SM_YL    184320
#define SM_CODE  188416    // 5*128 f32
#define SM_BFTR  190976    // 6*128 f32
#define SM_WOUT  194048    // 128 f32
#define SM_BYTES 194560

__device__ float g_norm[5][6];
__device__ float g_code[DEPTH * MAXB * HID];
__device__ __align__(16) unsigned char g_WfH[DEPTH][HID * 256];       // pre-swizzled [n][k] bf16
__device__ __align__(16) unsigned char g_WfL[DEPTH][HID * 256];
__device__ __align__(16) unsigned char g_FtH[(DEPTH + 1) * HID * 32]; // [stack][ch][16] bf16
__device__ __align__(16) unsigned char g_FtL[(DEPTH + 1) * HID * 32];

// ---------------- PTX helpers (all arch-agnostic, sm_80-era) ----------------
__device__ __forceinline__ uint32_t smem_u32(const void* p) {
    uint32_t a;
    asm("{ .reg .u64 t; cvta.to.shared.u64 t, %1; cvt.u32.u64 %0, t; }" : "=r"(a) : "l"(p));
    return a;
}
__device__ __forceinline__ void ldsm4(uint32_t* r, uint32_t addr) {
    asm volatile("ldmatrix.sync.aligned.m8n8.x4.shared.b16 {%0,%1,%2,%3}, [%4];"
                 : "=r"(r[0]), "=r"(r[1]), "=r"(r[2]), "=r"(r[3]) : "r"(addr));
}
__device__ __forceinline__ void mma16816(float* d, const uint32_t* a, uint32_t b0, uint32_t b1) {
    asm volatile("mma.sync.aligned.m16n8k16.row.col.f32.bf16.bf16.f32 "
                 "{%0,%1,%2,%3}, {%4,%5,%6,%7}, {%8,%9}, {%0,%1,%2,%3};"
                 : "+f"(d[0]), "+f"(d[1]), "+f"(d[2]), "+f"(d[3])
                 : "r"(a[0]), "r"(a[1]), "r"(a[2]), "r"(a[3]), "r"(b0), "r"(b1));
}
__device__ __forceinline__ void cp16(uint32_t daddr, const void* g) {
    asm volatile("cp.async.ca.shared.global [%0], [%1], 16;" :: "r"(daddr), "l"(g));
}
#define CP_COMMIT() asm volatile("cp.async.commit_group;" ::: "memory")
#define CP_WAIT()   asm volatile("cp.async.wait_group 0;"  ::: "memory")

// ---------------- prep kernels ----------------
__global__ void init_norm_kernel() {
    if (threadIdx.x == 0) {
        for (int m = 0; m <= 4; m++)
            for (int s = 0; s <= 5; s++) {
                int l = m + s;
                double f = 1.0;
                for (int q = l - m + 1; q <= l + m; q++) f *= (double)q;
                double K = sqrt((2.0 * l + 1.0) / (4.0 * M_PI) / f);
                g_norm[m][s] = (float)((m == 0) ? K : ((m & 1) ? -sqrt(2.0) * K : sqrt(2.0) * K));
            }
    }
}

__global__ void code_kernel(const float* __restrict__ a, const float* __restrict__ Wcode,
                            const float* __restrict__ bcode, const float* __restrict__ bfwd, int B) {
    int i = blockIdx.x, b = blockIdx.y, h = threadIdx.x;
    float acc = bfwd[i * HID + h] + bcode[i * HID + h];
    const float* wr = Wcode + ((long)i * HID + h) * CODEL;
    const float* av = a + (long)b * CODEL;
    #pragma unroll 4
    for (int c = 0; c < CODEL; c++) acc = fmaf(wr[c], av[c], acc);
    g_code[(i * B + b) * HID + h] = acc;
}

// pre-swizzled [n][k] bf16 image: row = 256B, seg = ((k>>3) ^ (n&7))
__global__ void prep_wfwd(const float* __restrict__ Wfwd) {
    int l = blockIdx.x;
    for (int idx = threadIdx.x; idx < HID * HID; idx += blockDim.x) {
        int n = idx >> 7, k = idx & 127;
        float w = Wfwd[l * HID * HID + idx];
        __nv_bfloat16 h = __float2bfloat16_rn(w);
        __nv_bfloat16 lo = __float2bfloat16_rn(w - __bfloat162float(h));
        int o = n * 256 + ((((k >> 3) ^ (n & 7)) << 4) | ((k & 7) * 2));
        *(__nv_bfloat16*)(g_WfH[l] + o) = h;
        *(__nv_bfloat16*)(g_WfL[l] + o) = lo;
    }
}

__global__ void prep_ftr(const float* __restrict__ Wftr) {
    int s = blockIdx.x;
    for (int idx = threadIdx.x; idx < HID * 16; idx += blockDim.x) {
        int ch = idx >> 4, k = idx & 15;
        float w = (k < 9) ? Wftr[s * HID * 9 + ch * 9 + k] : 0.0f;
        __nv_bfloat16 h = __float2bfloat16_rn(w);
        __nv_bfloat16 lo = __float2bfloat16_rn(w - __bfloat162float(h));
        int o = s * HID * 32 + ch * 32 + k * 2;
        *(__nv_bfloat16*)(g_FtH + o) = h;
        *(__nv_bfloat16*)(g_FtL + o) = lo;
    }
}

// ---------------- main kernel ----------------
__device__ __forceinline__ uint32_t pack_bf2(float x, float y) {
    __nv_bfloat162 v;
    v.x = __float2bfloat16_rn(x);
    v.y = __float2bfloat16_rn(y);
    return *reinterpret_cast<uint32_t*>(&v);
}

// filter GEMM: accF[16][4] = Y (x) Wftr_s  (3-pass hi/lo), acc pre-initialized
__device__ __forceinline__ void filter_gemm(float accF[16][4], uint32_t smb, int stack,
                                            int warp, int lane) {
    // A frag addresses (Y planes): row = 16w + (lane&7) + 8*((lane>>3)&1), seg k8 = lane>>4
    uint32_t arow = 16 * warp + (lane & 7) + 8 * ((lane >> 3) & 1);
    uint32_t aoff = arow * 32 + (lane >> 4) * 16;
    uint32_t aH[4], aL[4];
    ldsm4(aH, smb + SM_YH + aoff);
    ldsm4(aL, smb + SM_YL + aoff);
    // B: n = np*16 + (lane&7) + (lane>=16?8:0), k8 = (lane>>3)&1
    uint32_t bn = (lane & 7) + ((lane >> 4) << 3);
    uint32_t boff0 = stack * HID * 32 + bn * 32 + ((lane >> 3) & 1) * 16;
    #pragma unroll
    for (int np = 0; np < 8; np++) {
        uint32_t boff = boff0 + np * 16 * 32;
        uint32_t bH[4], bL[4];
        ldsm4(bH, smb + SM_FH + boff);
        ldsm4(bL, smb + SM_FL + boff);
        mma16816(accF[2 * np],     aH, bH[0], bH[1]);
        mma16816(accF[2 * np + 1], aH, bH[2], bH[3]);
        mma16816(accF[2 * np],     aH, bL[0], bL[1]);
        mma16816(accF[2 * np + 1], aH, bL[2], bL[3]);
        mma16816(accF[2 * np],     aL, bH[0], bH[1]);
        mma16816(accF[2 * np + 1], aL, bH[2], bH[3]);
    }
}

__global__ void __launch_bounds__(NTHREADS, 1)
main_kernel(const float* __restrict__ x, const float* __restrict__ bftr,
            const float* __restrict__ Wout, const float* __restrict__ bout,
            float* __restrict__ out, int N, int B) {
    extern __shared__ __align__(1024) char sm[];
    float* code_sh = (float*)(sm + SM_CODE);
    float* bftr_sh = (float*)(sm + SM_BFTR);
    float* wout_sh = (float*)(sm + SM_WOUT);

    const int t = threadIdx.x;
    const int warp = t >> 5, lane = t & 31;
    const uint32_t smb = smem_u32(sm);
    const long pt0 = (long)blockIdx.x * TILE;
    const int b = (int)(pt0 / N);

    // ---- stage resident small data: filter images, code, bftr, wout ----
    for (int i = t; i < 6 * HID * 32 / 16; i += NTHREADS) {
        cp16(smb + SM_FH + i * 16, g_FtH + i * 16);
        cp16(smb + SM_FL + i * 16, g_FtL + i * 16);
    }
    CP_COMMIT();
    for (int idx = t; idx < DEPTH * HID; idx += NTHREADS)
        code_sh[idx] = g_code[((idx >> 7) * B + b) * HID + (idx & 127)];
    for (int idx = t; idx < 6 * HID; idx += NTHREADS) bftr_sh[idx] = bftr[idx];
    if (t < HID) wout_sh[t] = Wout[t];

    // ---- spherical harmonics: thread t<128 computes its point ----
    if (t < TILE) {
        float Y[6][9];
        const float* xp = x + (pt0 + t) * 2;
        float theta = xp[0], phi = xp[1];
        float c = cosf(phi);
        float s2 = sqrtf(fmaxf(1.0f - c * c, 0.0f));
        float ct = cosf(theta), st = sinf(theta);
        float cmv = 1.0f, smv = 0.0f, pmm = 1.0f;
        #pragma unroll
        for (int m = 0; m <= 4; m++) {
            if (m > 0) {
                pmm *= -(2.0f * m - 1.0f) * s2;
                float cn = cmv * ct - smv * st;
                float sn = smv * ct + cmv * st;
                cmv = cn; smv = sn;
            }
            float Pm2 = pmm;
            float Pm1 = c * (2.0f * m + 1.0f) * pmm;
            #pragma unroll
            for (int s = 0; s <= 5; s++) {
                float P;
                if (s == 0)      P = Pm2;
                else if (s == 1) P = Pm1;
                else {
                    int l = m + s;
                    float Pl = ((2.0f * l - 1.0f) * c * Pm1 - (float)(l + m - 1) * Pm2) / (float)(l - m);
                    Pm2 = Pm1; Pm1 = Pl; P = Pl;
                }
                float base = g_norm[m][s] * P;
                if (m == 0) Y[s][4] = base;
                else { Y[s][4 + m] = base * cmv; Y[s][4 - m] = base * smv; }
            }
        }
        #pragma unroll
        for (int s = 0; s < 6; s++) {
            uint32_t* yh = (uint32_t*)(sm + SM_YH + s * 0 + t * 32);  // rows [pt][16]
            uint32_t* yl = (uint32_t*)(sm + SM_YL + t * 32);
            // note: Y planes hold only ONE stack at a time? No -- we need all 6.
            (void)yh; (void)yl;
        }
        // store all 6 stacks: layout [pt][16] per stack is too small; instead use
        // Y planes of 6 stacks stacked along k? Simpler: keep 6 stacks interleaved in
        // the 32B row as separate regions: we actually allocated only 4KB per plane.
        // Store stack s at row offset (s*0)... -- handled below with per-stack region.
        #pragma unroll
        for (int s = 0; s < 6; s++) {
            uint32_t w[8], wl[8];
            #pragma unroll
            for (int j = 0; j < 8; j++) {
                float a0 = (2 * j < 9) ? Y[s][2 * j] : 0.0f;
                float a1 = (2 * j + 1 < 9) ? Y[s][2 * j + 1] : 0.0f;
                __nv_bfloat16 h0 = __float2bfloat16_rn(a0), h1 = __float2bfloat16_rn(a1);
                float l0 = a0 - __bfloat162float(h0), l1 = a1 - __bfloat162float(h1);
                __nv_bfloat162 H; H.x = h0; H.y = h1;
                __nv_bfloat162 L; L.x = __float2bfloat16_rn(l0); L.y = __float2bfloat16_rn(l1);
                w[j]  = *reinterpret_cast<uint32_t*>(&H);
                wl[j] = *reinterpret_cast<uint32_t*>(&L);
            }
            // 6 stacks don't fit in 4KB... they do NOT overlap: we store the CURRENT
            // stack into per-stack slots inside ZH/ZL tails? Instead: reuse the fact
            // that stacks are consumed one per layer. Store all 6 into registers is
            // impossible across warps. => store stacks into the W stage buffer tail?
            // Simplest correct: store stack s rows at SM_YH + s*... but plane is 4KB
            // = 128*32B = one stack. FIX: store stacks 0..5 packed into FH/FL unused
            // space? Cleanest: enlarge Y region conceptually by using SM_YH for the
            // six stacks sequentially is wrong. We instead store all 6 stacks in the
            // Z planes' swizzle-free tail... Not available.
            // Resolution: Y stacks are stored in global scratch instead.
            uint32_t* gy = (uint32_t*)(g_FtH);  // placeholder, replaced below
            (void)gy; (void)w; (void)wl;
        }
    }
    __syncthreads();
    // NOTE: see g_Y usage below (global scratch for the 6 Y stacks).

    // ---- re-do Y store properly via global scratch g_Y ----
    // (declared after kernel; forward-compatible: actual implementation below)
    out[0] = out[0];  // placeholder never reached logically
    (void)wout_sh; (void)code_sh; (void)bftr_sh;
    (void)warp; (void)lane; (void)N;
}

// The above sketch had a Y-capacity bug; the real kernel follows.
// ---------------------------------------------------------------------------
#define SM2_ZH    0
#define SM2_ZL    32768
#define SM2_WH    65536
#define SM2_WL    98304
#define SM2_FH    131072                 // 6 stacks * 4096
#define SM2_FL    155648
#define SM2_YH    180224                 // 6 stacks * 4096 would be 24576; use 2 active
#define SM2_CODE  229376
#define SM2_BYTES 0

__global__ void __launch_bounds__(NTHREADS, 1)
main_kernel2(const float* __restrict__ x, const float* __restrict__ bftr,
             const float* __restrict__ Wout, const float* __restrict__ bout,
             float* __restrict__ out, int N, int B) {
    // SMEM map (recomputed to fit six Y stacks):
    //  ZH 0, ZL 32768, WH 65536, WL 98304,
    //  FH 131072 (24576), FL 155648 (24576),
    //  YH 180224 (6*4096=24576)?? too big with YL. -> Y hi/lo interleaved per row:
    //  Y row = 64B: [hi 32B | lo 32B], 6 stacks * 128 pts * 64B = 49152.
    //  Y at 180224..229376, code 229376.. -- exceeds 227KB budget.
    // Final layout: drop separate FH/FL staging; filter weights are tiny and
    // read straight from global via ldmatrix? ldmatrix needs SMEM. Instead:
    // filter B-frags are loaded ONCE per stack into registers? 8 regs/thread per
    // stack plane -> 6 stacks * (hi 8 + lo 8)... too many.
    // => Stage filter stack s into a small rotating buffer (2 stacks) at layer
    //    boundaries, alongside Wfwd staging. Buffer: 2 * 4096 * 2 planes = 16KB.
    extern __shared__ __align__(1024) char sm[];
    // layout:
    //  ZH 0 (32768), ZL 32768 (32768)
    //  WH 65536 (32768), WL 98304 (32768)
    //  FH 131072 (2 slots x 4096 = 8192), FL 139264 (8192)
    //  YHL 147456: 6 stacks x 128 pts x 64B = 49152  (row: hi 32B | lo 32B)
    //  code 196608 (2560), bftr 199168 (3072), wout 202240 (512)
    const int C_ZH = 0, C_ZL = 32768, C_WH = 65536, C_WL = 98304;
    const int C_FH = 131072, C_FL = 139264, C_Y = 147456;
    const int C_CODE = 196608, C_BFTR = 199168, C_WOUT = 202240;

    float* code_sh = (float*)(sm + C_CODE);
    float* bftr_sh = (float*)(sm + C_BFTR);
    float* wout_sh = (float*)(sm + C_WOUT);

    const int t = threadIdx.x;
    const int warp = t >> 5, lane = t & 31;
    const uint32_t smb = smem_u32(sm);
    const long pt0 = (long)blockIdx.x * TILE;
    const int b = (int)(pt0 / N);

    // stage filter stack 0 -> slot 0, stack 1 -> slot 1
    for (int i = t; i < 256; i += NTHREADS) {
        cp16(smb + C_FH + i * 16, g_FtH + i * 16);                    // stack0 hi
        cp16(smb + C_FL + i * 16, g_FtL + i * 16);                    // stack0 lo
        cp16(smb + C_FH + 4096 + i * 16, g_FtH + HID * 32 + i * 16);  // stack1 hi
        cp16(smb + C_FL + 4096 + i * 16, g_FtL + HID * 32 + i * 16);  // stack1 lo
    }
    CP_COMMIT();
    for (int idx = t; idx < DEPTH * HID; idx += NTHREADS)
        code_sh[idx] = g_code[((idx >> 7) * B + b) * HID + (idx & 127)];
    for (int idx = t; idx < 6 * HID; idx += NTHREADS) bftr_sh[idx] = bftr[idx];
    if (t < HID) wout_sh[t] = Wout[t];

    // ---- spherical harmonics ----
    if (t < TILE) {
        float Y[6][9];
        const float* xp = x + (pt0 + t) * 2;
        float theta = xp[0], phi = xp[1];
        float c = cosf(phi);
        float s2 = sqrtf(fmaxf(1.0f - c * c, 0.0f));
        float ct = cosf(theta), st = sinf(theta);
        float cmv = 1.0f, smv = 0.0f, pmm = 1.0f;
        #pragma unroll
        for (int m = 0; m <= 4; m++) {
            if (m > 0) {
                pmm *= -(2.0f * m - 1.0f) * s2;
                float cn = cmv * ct - smv * st;
                float sn = smv * ct + cmv * st;
                cmv = cn; smv = sn;
            }
            float Pm2 = pmm;
            float Pm1 = c * (2.0f * m + 1.0f) * pmm;
            #pragma unroll
            for (int s = 0; s <= 5; s++) {
                float P;
                if (s == 0)      P = Pm2;
                else if (s == 1) P = Pm1;
                else {
                    int l = m + s;
                    float Pl = ((2.0f * l - 1.0f) * c * Pm1 - (float)(l + m - 1) * Pm2) / (float)(l - m);
                    Pm2 = Pm1; Pm1 = Pl; P = Pl;
                }
                float base = g_norm[m][s] * P;
                if (m == 0) Y[s][4] = base;
                else { Y[s][4 + m] = base * cmv; Y[s][4 - m] = base * smv; }
            }
        }
        #pragma unroll
        for (int s = 0; s < 6; s++) {
            uint32_t* row = (uint32_t*)(sm + C_Y + (s * TILE + t) * 64);
            #pragma unroll
            for (int j = 0; j < 8; j++) {
                float a0 = (2 * j < 9) ? Y[s][2 * j] : 0.0f;
                float a1 = (2 * j + 1 < 9) ? Y[s][2 * j + 1] : 0.0f;
                __nv_bfloat16 h0 = __float2bfloat16_rn(a0), h1 = __float2bfloat16_rn(a1);
                float l0 = a0 - __bfloat162float(h0), l1 = a1 - __bfloat162float(h1);
                row[j]     = pack_bf2(__bfloat162float(h0) * 0.0f + a0 - l0, 0.0f) , // placeholder avoided
                row[j]     = (uint32_t)0;
                __nv_bfloat162 H; H.x = h0; H.y = h1;
                __nv_bfloat162 L; L.x = __float2bfloat16_rn(l0); L.y = __float2bfloat16_rn(l1);
                row[j]     = *reinterpret_cast<uint32_t*>(&H);
                row[8 + j] = *reinterpret_cast<uint32_t*>(&L);
            }
        }
    }
    CP_WAIT();
    __syncthreads();

    const float bo = bout[0];
    float accD[16][4], accF[16][4];

    // A-frag (Y): row = 16w + (lane&7) + 8*((lane>>3)&1); hi at +0, lo at +32;
    // k8 = lane>>4 -> +16
    const uint32_t yrow = 16 * warp + (lane & 7) + 8 * ((lane >> 3) & 1);
    const uint32_t yaH = smb + C_Y + yrow * 64 + (lane >> 4) * 16;
    const uint32_t yaL = yaH + 32;
    // B-frag (Wftr slot): n = np*16 + (lane&7) + (lane>=16?8:0); k8=(lane>>3)&1
    const uint32_t fbn = (lane & 7) + ((lane >> 4) << 3);
    const uint32_t fboff = fbn * 32 + ((lane >> 3) & 1) * 16;
    // A-frag (z planes): addr = row*256 + ((ks*2 + kh) ^ (row&7))*16
    const uint32_t zrow = yrow;
    const uint32_t zsel = (lane >> 4);             // kh
    // B-frag (W planes): n, k8 as filter
    const uint32_t wbn = fbn;
    const uint32_t wk8 = (lane >> 3) & 1;
    // epilogue store: rows er0 = 16w + lane/4, er1 = +8; col base cb = 2*(lane&3)
    const uint32_t er0 = 16 * warp + (lane >> 2), er1 = er0 + 8;
    const uint32_t ebyte = (lane & 3) * 4;

    // ---- z0 = filter(Y0) + bftr0 ----
    {
        #pragma unroll
        for (int nt = 0; nt < 16; nt++) {
            float v0 = bftr_sh[nt * 8 + 2 * (lane & 3)];
            float v1 = bftr_sh[nt * 8 + 2 * (lane & 3) + 1];
            accF[nt][0] = v0; accF[nt][1] = v1; accF[nt][2] = v0; accF[nt][3] = v1;
        }
        uint32_t aH[4], aL[4];
        ldsm4(aH, yaH + 0 * TILE * 64);
        ldsm4(aL, yaL + 0 * TILE * 64);
        #pragma unroll
        for (int np = 0; np < 8; np++) {
            uint32_t bH[4], bL[4];
            ldsm4(bH, smb + C_FH + 0 * 4096 + fboff + np * 16 * 32);
            ldsm4(bL, smb + C_FL + 0 * 4096 + fboff + np * 16 * 32);
            mma16816(accF[2 * np],     aH, bH[0], bH[1]);
            mma16816(accF[2 * np + 1], aH, bH[2], bH[3]);
            mma16816(accF[2 * np],     aH, bL[0], bL[1]);
            mma16816(accF[2 * np + 1], aH, bL[2], bL[3]);
            mma16816(accF[2 * np],     aL, bH[0], bH[1]);
            mma16816(accF[2 * np + 1], aL, bH[2], bH[3]);
        }
        // store z0 hi/lo to Z planes (own rows)
        #pragma unroll
        for (int nt = 0; nt < 16; nt++) {
            uint32_t seg0 = (uint32_t)(nt ^ (er0 & 7)) << 4;
            uint32_t seg1 = (uint32_t)(nt ^ (er1 & 7)) << 4;
            float z0 = accF[nt][0], z1 = accF[nt][1], z2 = accF[nt][2], z3 = accF[nt][3];
            __nv_bfloat16 h0 = __float2bfloat16_rn(z0), h1 = __float2bfloat16_rn(z1);
            __nv_bfloat16 h2 = __float2bfloat16_rn(z2), h3 = __float2bfloat16_rn(z3);
            *(uint32_t*)(sm + C_ZH + er0 * 256 + seg0 + ebyte) = pack_bf2(z0, z1);
            *(uint32_t*)(sm + C_ZH + er1 * 256 + seg1 + ebyte) = pack_bf2(z2, z3);
            *(uint32_t*)(sm + C_ZL + er0 * 256 + seg0 + ebyte) =
                pack_bf2(z0 - __bfloat162float(h0), z1 - __bfloat162float(h1));
            *(uint32_t*)(sm + C_ZL + er1 * 256 + seg1 + ebyte) =
                pack_bf2(z2 - __bfloat162float(h2), z3 - __bfloat162float(h3));
        }
    }
    __syncwarp();

    // ---- layers ----
    for (int i = 0; i < DEPTH; i++) {
        __syncthreads();   // all warps done reading W buffer (and filter slot) of prev layer
        // stage Wfwd[i] (64KB) and filter stack i+2 into slot i&1 (if exists)
        {
            const unsigned char* gh = g_WfH[i];
            const unsigned char* gl = g_WfL[i];
            for (int j = t; j < 2048; j += NTHREADS) {
                cp16(smb + C_WH + j * 16, gh + j * 16);
                cp16(smb + C_WL + j * 16, gl + j * 16);
            }
            if (i + 2 <= DEPTH) {
                int slot = i & 1;
                const unsigned char* fh = g_FtH + (i + 2) * HID * 32;
                const unsigned char* fl = g_FtL + (i + 2) * HID * 32;
                for (int j = t; j < 256; j += NTHREADS) {
                    cp16(smb + C_FH + slot * 4096 + j * 16, fh + j * 16);
                    cp16(smb + C_FL + slot * 4096 + j * 16, fl + j * 16);
                }
            }
            CP_COMMIT();
        }

        // filter GEMM for stack i+1 (slot (i+1)&1), overlapped with cp.async
        {
            int slot = (i + 1) & 1;
            #pragma unroll
            for (int nt = 0; nt < 16; nt++) {
                float v0 = bftr_sh[(i + 1) * HID + nt * 8 + 2 * (lane & 3)];
                float v1 = bftr_sh[(i + 1) * HID + nt * 8 + 2 * (lane & 3) + 1];
                accF[nt][0] = v0; accF[nt][1] = v1; accF[nt][2] = v0; accF[nt][3] = v1;
            }
            uint32_t aH[4], aL[4];
            ldsm4(aH, yaH + (i + 1) * TILE * 64);
            ldsm4(aL, yaL + (i + 1) * TILE * 64);
            #pragma unroll
            for (int np = 0; np < 8; np++) {
                uint32_t bH[4], bL[4];
                ldsm4(bH, smb + C_FH + slot * 4096 + fboff + np * 16 * 32);
                ldsm4(bL, smb + C_FL + slot * 4096 + fboff + np * 16 * 32);
                mma16816(accF[2 * np],     aH, bH[0], bH[1]);
                mma16816(accF[2 * np + 1], aH, bH[2], bH[3]);
                mma16816(accF[2 * np],     aH, bL[0], bL[1]);
                mma16816(accF[2 * np + 1], aH, bL[2], bL[3]);
                mma16816(accF[2 * np],     aL, bH[0], bH[1]);
                mma16816(accF[2 * np + 1], aL, bH[2], bH[3]);
            }
        }
        CP_WAIT();
        __syncthreads();   // W staged

        // D1 = z (x) Wfwd_i + code_i
        #pragma unroll
        for (int nt = 0; nt < 16; nt++) {
            float v0 = code_sh[i * HID + nt * 8 + 2 * (lane & 3)];
            float v1 = code_sh[i * HID + nt * 8 + 2 * (lane & 3) + 1];
            accD[nt][0] = v0; accD[nt][1] = v1; accD[nt][2] = v0; accD[nt][3] = v1;
        }
        #pragma unroll
        for (int ks = 0; ks < 8; ks++) {
            uint32_t aseg = ((uint32_t)(2 * ks + zsel) ^ (zrow & 7)) << 4;
            uint32_t aH[4], aL[4];
            ldsm4(aH, smb + C_ZH + zrow * 256 + aseg);
            ldsm4(aL, smb + C_ZL + zrow * 256 + aseg);
            #pragma unroll
            for (int np = 0; np < 8; np++) {
                uint32_t n0 = np * 16 + wbn;
                uint32_t bseg = ((uint32_t)(2 * ks + wk8) ^ (n0 & 7)) << 4;
                uint32_t boff = n0 * 256 + bseg;
                uint32_t bH[4], bL[4];
                ldsm4(bH, smb + C_WH + boff);
                ldsm4(bL, smb + C_WL + boff);
                mma16816(accD[2 * np],     aH, bH[0], bH[1]);
                mma16816(accD[2 * np + 1], aH, bH[2], bH[3]);
                mma16816(accD[2 * np],     aH, bL[0], bL[1]);
                mma16816(accD[2 * np + 1], aH, bL[2], bL[3]);
                mma16816(accD[2 * np],     aL, bH[0], bH[1]);
                mma16816(accD[2 * np + 1], aL, bH[2], bH[3]);
            }
        }

        if (i < DEPTH - 1) {
            // z_new = D1 * D2 -> hi/lo -> Z planes (own rows)
            __syncwarp();
            #pragma unroll
            for (int nt = 0; nt < 16; nt++) {
                uint32_t seg0 = (uint32_t)(nt ^ (er0 & 7)) << 4;
                uint32_t seg1 = (uint32_t)(nt ^ (er1 & 7)) << 4;
                float z0 = accD[nt][0] * accF[nt][0];
                float z1 = accD[nt][1] * accF[nt][1];
                float z2 = accD[nt][2] * accF[nt][2];
                float z3 = accD[nt][3] * accF[nt][3];
                __nv_bfloat16 h0 = __float2bfloat16_rn(z0), h1 = __float2bfloat16_rn(z1);
                __nv_bfloat16 h2 = __float2bfloat16_rn(z2), h3 = __float2bfloat16_rn(z3);
                *(uint32_t*)(sm + C_ZH + er0 * 256 + seg0 + ebyte) = pack_bf2(z0, z1);
                *(uint32_t*)(sm + C_ZH + er1 * 256 + seg1 + ebyte) = pack_bf2(z2, z3);
                *(uint32_t*)(sm + C_ZL + er0 * 256 + seg0 + ebyte) =
                    pack_bf2(z0 - __bfloat162float(h0), z1 - __bfloat162float(h1));
                *(uint32_t*)(sm + C_ZL + er1 * 256 + seg1 + ebyte) =
                    pack_bf2(z2 - __bfloat162float(h2), z3 - __bfloat162float(h3));
            }
            __syncwarp();
        } else {
            // final: out = sum_ch (D1*D2)*wout + bout
            float p0 = 0.0f, p1 = 0.0f;
            #pragma unroll
            for (int nt = 0; nt < 16; nt++) {
                float w0 = wout_sh[nt * 8 + 2 * (lane & 3)];
                float w1 = wout_sh[nt * 8 + 2 * (lane & 3) + 1];
                p0 = fmaf(accD[nt][0] * accF[nt][0], w0, p0);
                p0 = fmaf(accD[nt][1] * accF[nt][1], w1, p0);
                p1 = fmaf(accD[nt][2] * accF[nt][2], w0, p1);
                p1 = fmaf(accD[nt][3] * accF[nt][3], w1, p1);
            }
            p0 += __shfl_xor_sync(0xffffffffu, p0, 1);
            p0 += __shfl_xor_sync(0xffffffffu, p0, 2);
            p1 += __shfl_xor_sync(0xffffffffu, p1, 1);
            p1 += __shfl_xor_sync(0xffffffffu, p1, 2);
            if ((lane & 3) == 0) {
                out[pt0 + er0] = p0 + bo;
                out[pt0 + er1] = p1 + bo;
            }
        }
    }
}

// ---------------------------------------------------------------------------
extern "C" void kernel_launch(void* const* d_in, const int* in_sizes, int n_in,
                              void* d_out, int out_size) {
    const float* x     = (const float*)d_in[0];
    const float* a     = (const float*)d_in[1];
    const float* Wftr  = (const float*)d_in[2];
    const float* bftr  = (const float*)d_in[3];
    const float* Wfwd  = (const float*)d_in[4];
    const float* bfwd  = (const float*)d_in[5];
    const float* Wcode = (const float*)d_in[6];
    const float* bcode = (const float*)d_in[7];
    const float* Wout  = (const float*)d_in[8];
    const float* bout  = (const float*)d_in[9];
    float* out = (float*)d_out;

    int  B  = in_sizes[1] / CODEL;
    long BN = (long)in_sizes[0] / 2;
    int  N  = (int)(BN / B);

    init_norm_kernel<<<1, 32>>>();
    dim3 gcode(DEPTH, B);
    code_kernel<<<gcode, HID>>>(a, Wcode, bcode, bfwd, B);
    prep_wfwd<<<DEPTH, 256>>>(Wfwd);
    prep_ftr<<<DEPTH + 1, 256>>>(Wftr);

    const int smem = 202752;  // covers layout incl. wout at 202240 (+512)
    cudaFuncSetAttribute(main_kernel2, cudaFuncAttributeMaxDynamicSharedMemorySize, smem);
    int blocks = (int)(BN / TILE);
    main_kernel2<<<blocks, NTHREADS, smem>>>(x, bftr, Wout, bout, out, N, B);

    if ((long)out_size >= BN * 3) {
        cudaMemcpyAsync(out + BN, x, (size_t)BN * 2 * sizeof(float),
                        cudaMemcpyDeviceToDevice, 0);
    }
}

// round 6
// speedup vs baseline: 3.1573x; 1.0600x over previous
#include <cuda_runtime.h>
#include <cuda_bf16.h>
#include <math.h>
#include <stdint.h>

#define DEPTH   5
#define HID     128
#define CODEL   400
#define MAXB    16
#define TILE    128
#define NTH     512

// ---- SMEM byte offsets ----
#define C_ZH    0
#define C_ZL    32768
#define C_WH    65536
#define C_WL    98304
#define C_FH    131072      // 2 slots x 4096
#define C_FL    139264
#define C_Y     147456      // 6 stacks x 128 pts x 64B (hi 32B | lo 32B)
#define C_CODE  196608
#define C_BFTR  199168
#define C_WOUT  202240
#define SMEM_SZ 202752
#define C_OUTP  C_Y         // reused after final filter GEMM

__device__ float g_norm[5][6];
__device__ float g_code[DEPTH * MAXB * HID];
__device__ __align__(16) unsigned char g_WfH[DEPTH][HID * 256];       // pre-swizzled [n][k]
__device__ __align__(16) unsigned char g_WfL[DEPTH][HID * 256];
__device__ __align__(16) unsigned char g_FtH[(DEPTH + 1) * HID * 32]; // [stack][ch][16k]
__device__ __align__(16) unsigned char g_FtL[(DEPTH + 1) * HID * 32];

// ---------------- PTX helpers (arch-agnostic) ----------------
__device__ __forceinline__ uint32_t smem_u32(const void* p) {
    uint32_t a;
    asm("{ .reg .u64 t; cvta.to.shared.u64 t, %1; cvt.u32.u64 %0, t; }" : "=r"(a) : "l"(p));
    return a;
}
__device__ __forceinline__ void ldsm4(uint32_t* r, uint32_t addr) {
    asm volatile("ldmatrix.sync.aligned.m8n8.x4.shared.b16 {%0,%1,%2,%3}, [%4];"
                 : "=r"(r[0]), "=r"(r[1]), "=r"(r[2]), "=r"(r[3]) : "r"(addr));
}
__device__ __forceinline__ void mma16816(float* d, const uint32_t* a, uint32_t b0, uint32_t b1) {
    asm volatile("mma.sync.aligned.m16n8k16.row.col.f32.bf16.bf16.f32 "
                 "{%0,%1,%2,%3}, {%4,%5,%6,%7}, {%8,%9}, {%0,%1,%2,%3};"
                 : "+f"(d[0]), "+f"(d[1]), "+f"(d[2]), "+f"(d[3])
                 : "r"(a[0]), "r"(a[1]), "r"(a[2]), "r"(a[3]), "r"(b0), "r"(b1));
}
__device__ __forceinline__ void cp16(uint32_t daddr, const void* g) {
    asm volatile("cp.async.ca.shared.global [%0], [%1], 16;" :: "r"(daddr), "l"(g));
}
#define CP_COMMIT() asm volatile("cp.async.commit_group;" ::: "memory")
#define CP_WAIT()   asm volatile("cp.async.wait_group 0;"  ::: "memory")

__device__ __forceinline__ uint32_t pack_bf2(float x, float y) {
    __nv_bfloat162 v;
    v.x = __float2bfloat16_rn(x);
    v.y = __float2bfloat16_rn(y);
    return *reinterpret_cast<uint32_t*>(&v);
}

// ---------------- single merged prep kernel ----------------
__global__ void prep_all(const float* __restrict__ a, const float* __restrict__ Wcode,
                         const float* __restrict__ bcode, const float* __restrict__ bfwd,
                         const float* __restrict__ Wfwd, const float* __restrict__ Wftr,
                         int B) {
    int blk = blockIdx.x;
    if (blk == 0 && threadIdx.x == 0) {
        for (int m = 0; m <= 4; m++)
            for (int s = 0; s <= 5; s++) {
                int l = m + s;
                double f = 1.0;
                for (int q = l - m + 1; q <= l + m; q++) f *= (double)q;
                double K = sqrt((2.0 * l + 1.0) / (4.0 * M_PI) / f);
                g_norm[m][s] = (float)((m == 0) ? K : ((m & 1) ? -sqrt(2.0) * K : sqrt(2.0) * K));
            }
    }
    if (blk < DEPTH) {
        // Wfwd layer blk -> swizzled bf16 hi/lo images
        int l = blk;
        for (int idx = threadIdx.x; idx < HID * HID; idx += blockDim.x) {
            int n = idx >> 7, k = idx & 127;
            float w = Wfwd[l * HID * HID + idx];
            __nv_bfloat16 h = __float2bfloat16_rn(w);
            __nv_bfloat16 lo = __float2bfloat16_rn(w - __bfloat162float(h));
            int o = n * 256 + ((((k >> 3) ^ (n & 7)) << 4) | ((k & 7) * 2));
            *(__nv_bfloat16*)(g_WfH[l] + o) = h;
            *(__nv_bfloat16*)(g_WfL[l] + o) = lo;
        }
    } else if (blk < 2 * DEPTH + 1) {
        int s = blk - DEPTH;
        for (int idx = threadIdx.x; idx < HID * 16; idx += blockDim.x) {
            int ch = idx >> 4, k = idx & 15;
            float w = (k < 9) ? Wftr[s * HID * 9 + ch * 9 + k] : 0.0f;
            __nv_bfloat16 h = __float2bfloat16_rn(w);
            __nv_bfloat16 lo = __float2bfloat16_rn(w - __bfloat162float(h));
            int o = s * HID * 32 + ch * 32 + k * 2;
            *(__nv_bfloat16*)(g_FtH + o) = h;
            *(__nv_bfloat16*)(g_FtL + o) = lo;
        }
    } else {
        int r = blk - (2 * DEPTH + 1);
        int i = r / B, b = r % B;
        int h = threadIdx.x;
        if (h < HID) {
            float acc = bfwd[i * HID + h] + bcode[i * HID + h];
            const float* wr = Wcode + ((long)i * HID + h) * CODEL;
            const float* av = a + (long)b * CODEL;
            #pragma unroll 4
            for (int c = 0; c < CODEL; c++) acc = fmaf(wr[c], av[c], acc);
            g_code[(i * B + b) * HID + h] = acc;
        }
    }
}

// ---------------- main kernel: 512 threads, 16 warps ----------------
// warp w: wm = w&7 (16 points), wn = w>>3 (64-channel half)
__global__ void __launch_bounds__(NTH, 1)
main_kernel(const float* __restrict__ x, const float* __restrict__ bftr,
            const float* __restrict__ Wout, const float* __restrict__ bout,
            float* __restrict__ out, int N, int B) {
    extern __shared__ __align__(1024) char sm[];
    float* code_sh = (float*)(sm + C_CODE);
    float* bftr_sh = (float*)(sm + C_BFTR);
    float* wout_sh = (float*)(sm + C_WOUT);
    float* outp    = (float*)(sm + C_OUTP);

    const int t = threadIdx.x;
    const int warp = t >> 5, lane = t & 31;
    const int wm = warp & 7, wn = warp >> 3;
    const int chb = wn * 64;
    const uint32_t smb = smem_u32(sm);
    const long pt0 = (long)blockIdx.x * TILE;
    const int b = (int)(pt0 / N);

    // stage filter stacks 0,1 into slots 0,1
    for (int j = t; j < 256; j += NTH) {
        cp16(smb + C_FH + j * 16, g_FtH + j * 16);
        cp16(smb + C_FL + j * 16, g_FtL + j * 16);
        cp16(smb + C_FH + 4096 + j * 16, g_FtH + HID * 32 + j * 16);
        cp16(smb + C_FL + 4096 + j * 16, g_FtL + HID * 32 + j * 16);
    }
    CP_COMMIT();
    for (int idx = t; idx < DEPTH * HID; idx += NTH)
        code_sh[idx] = g_code[((idx >> 7) * B + b) * HID + (idx & 127)];
    for (int idx = t; idx < 6 * HID; idx += NTH) bftr_sh[idx] = bftr[idx];
    if (t < HID) wout_sh[t] = Wout[t];

    // ---- spherical harmonics: t<128 computes one point, hi/lo -> Y rows ----
    if (t < TILE) {
        float Y[6][9];
        const float* xp = x + (pt0 + t) * 2;
        float theta = xp[0], phi = xp[1];
        float c = cosf(phi);
        float s2 = sqrtf(fmaxf(1.0f - c * c, 0.0f));
        float ct = cosf(theta), st = sinf(theta);
        float cmv = 1.0f, smv = 0.0f, pmm = 1.0f;
        #pragma unroll
        for (int m = 0; m <= 4; m++) {
            if (m > 0) {
                pmm *= -(2.0f * m - 1.0f) * s2;
                float cn = cmv * ct - smv * st;
                float sn = smv * ct + cmv * st;
                cmv = cn; smv = sn;
            }
            float Pm2 = pmm;
            float Pm1 = c * (2.0f * m + 1.0f) * pmm;
            #pragma unroll
            for (int s = 0; s <= 5; s++) {
                float P;
                if (s == 0)      P = Pm2;
                else if (s == 1) P = Pm1;
                else {
                    int l = m + s;
                    float Pl = ((2.0f * l - 1.0f) * c * Pm1 - (float)(l + m - 1) * Pm2) / (float)(l - m);
                    Pm2 = Pm1; Pm1 = Pl; P = Pl;
                }
                float base = g_norm[m][s] * P;
                if (m == 0) Y[s][4] = base;
                else { Y[s][4 + m] = base * cmv; Y[s][4 - m] = base * smv; }
            }
        }
        #pragma unroll
        for (int s = 0; s < 6; s++) {
            uint32_t* row = (uint32_t*)(sm + C_Y + (s * TILE + t) * 64);
            #pragma unroll
            for (int j = 0; j < 8; j++) {
                float a0 = (2 * j < 9) ? Y[s][2 * j] : 0.0f;
                float a1 = (2 * j + 1 < 9) ? Y[s][2 * j + 1] : 0.0f;
                __nv_bfloat16 h0 = __float2bfloat16_rn(a0), h1 = __float2bfloat16_rn(a1);
                row[j]     = pack_bf2(a0, a1);
                row[8 + j] = pack_bf2(a0 - __bfloat162float(h0), a1 - __bfloat162float(h1));
            }
        }
    }
    CP_WAIT();
    __syncthreads();

    const float bo = bout[0];
    float accD[8][4], accF[8][4];

    // per-lane fragment addressing (validated in round 3)
    const uint32_t yrow  = 16 * wm + (lane & 7) + 8 * ((lane >> 3) & 1);
    const uint32_t yaH   = smb + C_Y + yrow * 64 + (lane >> 4) * 16;
    const uint32_t yaL   = yaH + 32;
    const uint32_t fbn   = (lane & 7) + ((lane >> 4) << 3);
    const uint32_t zrow  = yrow;
    const uint32_t zsel  = lane >> 4;
    const uint32_t wk8   = (lane >> 3) & 1;
    const uint32_t er0   = 16 * wm + (lane >> 2), er1 = er0 + 8;
    const uint32_t ebyte = (lane & 3) * 4;
    const int cb2 = chb + 2 * (lane & 3);

    // ---- z0 = filter(Y0) + bftr0  (each warp: its 16 pts x 64 ch) ----
    {
        #pragma unroll
        for (int nt = 0; nt < 8; nt++) {
            float v0 = bftr_sh[cb2 + nt * 8];
            float v1 = bftr_sh[cb2 + nt * 8 + 1];
            accF[nt][0] = v0; accF[nt][1] = v1; accF[nt][2] = v0; accF[nt][3] = v1;
        }
        uint32_t aH[4], aL[4];
        ldsm4(aH, yaH);
        ldsm4(aL, yaL);
        #pragma unroll
        for (int np = 0; np < 4; np++) {
            uint32_t boff = (uint32_t)(chb + np * 16 + fbn) * 32 + wk8 * 16;
            uint32_t bH[4], bL[4];
            ldsm4(bH, smb + C_FH + boff);
            ldsm4(bL, smb + C_FL + boff);
            mma16816(accF[2 * np],     aH, bH[0], bH[1]);
            mma16816(accF[2 * np + 1], aH, bH[2], bH[3]);
            mma16816(accF[2 * np],     aH, bL[0], bL[1]);
            mma16816(accF[2 * np + 1], aH, bL[2], bL[3]);
            mma16816(accF[2 * np],     aL, bH[0], bH[1]);
            mma16816(accF[2 * np + 1], aL, bH[2], bH[3]);
        }
        #pragma unroll
        for (int nt = 0; nt < 8; nt++) {
            uint32_t kc = (uint32_t)(wn * 8 + nt);
            uint32_t seg0 = (kc ^ (er0 & 7)) << 4;
            uint32_t seg1 = (kc ^ (er1 & 7)) << 4;
            float z0 = accF[nt][0], z1 = accF[nt][1], z2 = accF[nt][2], z3 = accF[nt][3];
            __nv_bfloat16 h0 = __float2bfloat16_rn(z0), h1 = __float2bfloat16_rn(z1);
            __nv_bfloat16 h2 = __float2bfloat16_rn(z2), h3 = __float2bfloat16_rn(z3);
            *(uint32_t*)(sm + C_ZH + er0 * 256 + seg0 + ebyte) = pack_bf2(z0, z1);
            *(uint32_t*)(sm + C_ZH + er1 * 256 + seg1 + ebyte) = pack_bf2(z2, z3);
            *(uint32_t*)(sm + C_ZL + er0 * 256 + seg0 + ebyte) =
                pack_bf2(z0 - __bfloat162float(h0), z1 - __bfloat162float(h1));
            *(uint32_t*)(sm + C_ZL + er1 * 256 + seg1 + ebyte) =
                pack_bf2(z2 - __bfloat162float(h2), z3 - __bfloat162float(h3));
        }
    }

    // ---- layers ----
    for (int i = 0; i < DEPTH; i++) {
        __syncthreads();   // B1: z stores visible; W/filter-slot consumers done
        {
            const unsigned char* gh = g_WfH[i];
            const unsigned char* gl = g_WfL[i];
            for (int j = t; j < 2048; j += NTH) {
                cp16(smb + C_WH + j * 16, gh + j * 16);
                cp16(smb + C_WL + j * 16, gl + j * 16);
            }
            if (i + 2 <= DEPTH) {
                int slot = i & 1;
                const unsigned char* fh = g_FtH + (i + 2) * HID * 32;
                const unsigned char* fl = g_FtL + (i + 2) * HID * 32;
                for (int j = t; j < 256; j += NTH) {
                    cp16(smb + C_FH + slot * 4096 + j * 16, fh + j * 16);
                    cp16(smb + C_FL + slot * 4096 + j * 16, fl + j * 16);
                }
            }
            CP_COMMIT();
        }

        // filter GEMM for stack i+1 (slot (i+1)&1), overlapped with cp.async
        {
            int slot = (i + 1) & 1;
            #pragma unroll
            for (int nt = 0; nt < 8; nt++) {
                float v0 = bftr_sh[(i + 1) * HID + cb2 + nt * 8];
                float v1 = bftr_sh[(i + 1) * HID + cb2 + nt * 8 + 1];
                accF[nt][0] = v0; accF[nt][1] = v1; accF[nt][2] = v0; accF[nt][3] = v1;
            }
            uint32_t aH[4], aL[4];
            ldsm4(aH, yaH + (i + 1) * TILE * 64);
            ldsm4(aL, yaL + (i + 1) * TILE * 64);
            #pragma unroll
            for (int np = 0; np < 4; np++) {
                uint32_t boff = (uint32_t)slot * 4096 + (uint32_t)(chb + np * 16 + fbn) * 32 + wk8 * 16;
                uint32_t bH[4], bL[4];
                ldsm4(bH, smb + C_FH + boff);
                ldsm4(bL, smb + C_FL + boff);
                mma16816(accF[2 * np],     aH, bH[0], bH[1]);
                mma16816(accF[2 * np + 1], aH, bH[2], bH[3]);
                mma16816(accF[2 * np],     aH, bL[0], bL[1]);
                mma16816(accF[2 * np + 1], aH, bL[2], bL[3]);
                mma16816(accF[2 * np],     aL, bH[0], bH[1]);
                mma16816(accF[2 * np + 1], aL, bH[2], bH[3]);
            }
        }
        CP_WAIT();
        __syncthreads();   // B2: W staged

        // main GEMM: accD = z (x) Wfwd_i + code_i   (16 pts x 64 ch per warp)
        #pragma unroll
        for (int nt = 0; nt < 8; nt++) {
            float v0 = code_sh[i * HID + cb2 + nt * 8];
            float v1 = code_sh[i * HID + cb2 + nt * 8 + 1];
            accD[nt][0] = v0; accD[nt][1] = v1; accD[nt][2] = v0; accD[nt][3] = v1;
        }
        #pragma unroll
        for (int ks = 0; ks < 8; ks++) {
            uint32_t aseg = ((uint32_t)(2 * ks + zsel) ^ (zrow & 7)) << 4;
            uint32_t aH[4], aL[4];
            ldsm4(aH, smb + C_ZH + zrow * 256 + aseg);
            ldsm4(aL, smb + C_ZL + zrow * 256 + aseg);
            #pragma unroll
            for (int np = 0; np < 4; np++) {
                uint32_t n0 = (uint32_t)(chb + np * 16) + fbn;
                uint32_t bseg = ((uint32_t)(2 * ks + wk8) ^ (n0 & 7)) << 4;
                uint32_t boff = n0 * 256 + bseg;
                uint32_t bH[4], bL[4];
                ldsm4(bH, smb + C_WH + boff);
                ldsm4(bL, smb + C_WL + boff);
                mma16816(accD[2 * np],     aH, bH[0], bH[1]);
                mma16816(accD[2 * np + 1], aH, bH[2], bH[3]);
                mma16816(accD[2 * np],     aH, bL[0], bL[1]);
                mma16816(accD[2 * np + 1], aH, bL[2], bL[3]);
                mma16816(accD[2 * np],     aL, bH[0], bH[1]);
                mma16816(accD[2 * np + 1], aL, bH[2], bH[3]);
            }
        }

        if (i < DEPTH - 1) {
            __syncthreads();   // B3: partner warp done reading old z rows
            #pragma unroll
            for (int nt = 0; nt < 8; nt++) {
                uint32_t kc = (uint32_t)(wn * 8 + nt);
                uint32_t seg0 = (kc ^ (er0 & 7)) << 4;
                uint32_t seg1 = (kc ^ (er1 & 7)) << 4;
                float z0 = accD[nt][0] * accF[nt][0];
                float z1 = accD[nt][1] * accF[nt][1];
                float z2 = accD[nt][2] * accF[nt][2];
                float z3 = accD[nt][3] * accF[nt][3];
                __nv_bfloat16 h0 = __float2bfloat16_rn(z0), h1 = __float2bfloat16_rn(z1);
                __nv_bfloat16 h2 = __float2bfloat16_rn(z2), h3 = __float2bfloat16_rn(z3);
                *(uint32_t*)(sm + C_ZH + er0 * 256 + seg0 + ebyte) = pack_bf2(z0, z1);
                *(uint32_t*)(sm + C_ZH + er1 * 256 + seg1 + ebyte) = pack_bf2(z2, z3);
                *(uint32_t*)(sm + C_ZL + er0 * 256 + seg0 + ebyte) =
                    pack_bf2(z0 - __bfloat162float(h0), z1 - __bfloat162float(h1));
                *(uint32_t*)(sm + C_ZL + er1 * 256 + seg1 + ebyte) =
                    pack_bf2(z2 - __bfloat162float(h2), z3 - __bfloat162float(h3));
            }
        } else {
            // final: partial dot over this warp's 64 channels
            float p0 = 0.0f, p1 = 0.0f;
            #pragma unroll
            for (int nt = 0; nt < 8; nt++) {
                float w0 = wout_sh[cb2 + nt * 8];
                float w1 = wout_sh[cb2 + nt * 8 + 1];
                p0 = fmaf(accD[nt][0] * accF[nt][0], w0, p0);
                p0 = fmaf(accD[nt][1] * accF[nt][1], w1, p0);
                p1 = fmaf(accD[nt][2] * accF[nt][2], w0, p1);
                p1 = fmaf(accD[nt][3] * accF[nt][3], w1, p1);
            }
            p0 += __shfl_xor_sync(0xffffffffu, p0, 1);
            p0 += __shfl_xor_sync(0xffffffffu, p0, 2);
            p1 += __shfl_xor_sync(0xffffffffu, p1, 1);
            p1 += __shfl_xor_sync(0xffffffffu, p1, 2);
            __syncthreads();   // Y reads all done (pre-B2); safe to reuse as outp
            if ((lane & 3) == 0) {
                outp[wn * TILE + er0] = p0;
                outp[wn * TILE + er1] = p1;
            }
            __syncthreads();
            if (t < TILE)
                out[pt0 + t] = outp[t] + outp[TILE + t] + bo;
        }
    }
}

// ---------------------------------------------------------------------------
extern "C" void kernel_launch(void* const* d_in, const int* in_sizes, int n_in,
                              void* d_out, int out_size) {
    const float* x     = (const float*)d_in[0];
    const float* a     = (const float*)d_in[1];
    const float* Wftr  = (const float*)d_in[2];
    const float* bftr  = (const float*)d_in[3];
    const float* Wfwd  = (const float*)d_in[4];
    const float* bfwd  = (const float*)d_in[5];
    const float* Wcode = (const float*)d_in[6];
    const float* bcode = (const float*)d_in[7];
    const float* Wout  = (const float*)d_in[8];
    const float* bout  = (const float*)d_in[9];
    float* out = (float*)d_out;

    int  B  = in_sizes[1] / CODEL;
    long BN = (long)in_sizes[0] / 2;
    int  N  = (int)(BN / B);

    prep_all<<<2 * DEPTH + 1 + DEPTH * B, 128>>>(a, Wcode, bcode, bfwd, Wfwd, Wftr, B);

    cudaFuncSetAttribute(main_kernel, cudaFuncAttributeMaxDynamicSharedMemorySize, SMEM_SZ);
    int blocks = (int)(BN / TILE);
    main_kernel<<<blocks, NTH, SMEM_SZ>>>(x, bftr, Wout, bout, out, N, B);

    if ((long)out_size >= BN * 3) {
        cudaMemcpyAsync(out + BN, x, (size_t)BN * 2 * sizeof(float),
                        cudaMemcpyDeviceToDevice, 0);
    }
}

// round 17
// speedup vs baseline: 3.2496x; 1.0292x over previous
#include <cuda_runtime.h>
#include <cuda_bf16.h>
#include <math.h>
#include <stdint.h>

#define DEPTH   5
#define HID     128
#define CODEL   400
#define MAXB    16
#define TILE    128
#define NTH     512

// ---- SMEM byte offsets ----
#define C_ZH    0           // z hi plane: 128 rows x 256B (swizzled)
#define C_ZL    32768
#define C_W     65536       // 2 half-K bufs x (hi 16K + lo 16K) = 64K
#define C_FH    131072      // 2 slots x 4096
#define C_FL    139264
#define C_Y     147456      // 6 stacks x 128 pts x 80B (hi 32 | lo 32 | pad 16)
#define C_CODE  208896
#define C_BFTR  211456
#define C_WOUT  214528
#define SMEM_SZ 215040

__device__ float g_norm[5][6];
__device__ float g_code[DEPTH * MAXB * HID];
__device__ __align__(16) unsigned char g_WfH[DEPTH][HID * 256];       // pre-swizzled [n][k]
__device__ __align__(16) unsigned char g_WfL[DEPTH][HID * 256];
__device__ __align__(16) unsigned char g_FtH[(DEPTH + 1) * HID * 32]; // [stack][ch][16k]
__device__ __align__(16) unsigned char g_FtL[(DEPTH + 1) * HID * 32];

// ---------------- PTX helpers (arch-agnostic) ----------------
__device__ __forceinline__ uint32_t smem_u32(const void* p) {
    uint32_t a;
    asm("{ .reg .u64 t; cvta.to.shared.u64 t, %1; cvt.u32.u64 %0, t; }" : "=r"(a) : "l"(p));
    return a;
}
__device__ __forceinline__ void ldsm4(uint32_t* r, uint32_t addr) {
    asm volatile("ldmatrix.sync.aligned.m8n8.x4.shared.b16 {%0,%1,%2,%3}, [%4];"
                 : "=r"(r[0]), "=r"(r[1]), "=r"(r[2]), "=r"(r[3]) : "r"(addr));
}
__device__ __forceinline__ void mma16816(float* d, const uint32_t* a, uint32_t b0, uint32_t b1) {
    asm volatile("mma.sync.aligned.m16n8k16.row.col.f32.bf16.bf16.f32 "
                 "{%0,%1,%2,%3}, {%4,%5,%6,%7}, {%8,%9}, {%0,%1,%2,%3};"
                 : "+f"(d[0]), "+f"(d[1]), "+f"(d[2]), "+f"(d[3])
                 : "r"(a[0]), "r"(a[1]), "r"(a[2]), "r"(a[3]), "r"(b0), "r"(b1));
}
__device__ __forceinline__ void cp16(uint32_t daddr, const void* g) {
    asm volatile("cp.async.ca.shared.global [%0], [%1], 16;" :: "r"(daddr), "l"(g));
}
#define CP_COMMIT() asm volatile("cp.async.commit_group;" ::: "memory")
#define CP_WAIT0()  asm volatile("cp.async.wait_group 0;"  ::: "memory")
#define CP_WAIT1()  asm volatile("cp.async.wait_group 1;"  ::: "memory")
#define CP_WAIT2()  asm volatile("cp.async.wait_group 2;"  ::: "memory")

__device__ __forceinline__ uint32_t pack_bf2(float x, float y) {
    __nv_bfloat162 v;
    v.x = __float2bfloat16_rn(x);
    v.y = __float2bfloat16_rn(y);
    return *reinterpret_cast<uint32_t*>(&v);
}

// ---------------- single merged prep kernel ----------------
__global__ void prep_all(const float* __restrict__ a, const float* __restrict__ Wcode,
                         const float* __restrict__ bcode, const float* __restrict__ bfwd,
                         const float* __restrict__ Wfwd, const float* __restrict__ Wftr,
                         int B) {
    int blk = blockIdx.x;
    if (blk == 0 && threadIdx.x == 0) {
        for (int m = 0; m <= 4; m++)
            for (int s = 0; s <= 5; s++) {
                int l = m + s;
                double f = 1.0;
                for (int q = l - m + 1; q <= l + m; q++) f *= (double)q;
                double K = sqrt((2.0 * l + 1.0) / (4.0 * M_PI) / f);
                g_norm[m][s] = (float)((m == 0) ? K : ((m & 1) ? -sqrt(2.0) * K : sqrt(2.0) * K));
            }
    }
    if (blk < DEPTH) {
        int l = blk;
        for (int idx = threadIdx.x; idx < HID * HID; idx += blockDim.x) {
            int n = idx >> 7, k = idx & 127;
            float w = Wfwd[l * HID * HID + idx];
            __nv_bfloat16 h = __float2bfloat16_rn(w);
            __nv_bfloat16 lo = __float2bfloat16_rn(w - __bfloat162float(h));
            int o = n * 256 + ((((k >> 3) ^ (n & 7)) << 4) | ((k & 7) * 2));
            *(__nv_bfloat16*)(g_WfH[l] + o) = h;
            *(__nv_bfloat16*)(g_WfL[l] + o) = lo;
        }
    } else if (blk < 2 * DEPTH + 1) {
        int s = blk - DEPTH;
        for (int idx = threadIdx.x; idx < HID * 16; idx += blockDim.x) {
            int ch = idx >> 4, k = idx & 15;
            float w = (k < 9) ? Wftr[s * HID * 9 + ch * 9 + k] : 0.0f;
            __nv_bfloat16 h = __float2bfloat16_rn(w);
            __nv_bfloat16 lo = __float2bfloat16_rn(w - __bfloat162float(h));
            int o = s * HID * 32 + ch * 32 + k * 2;
            *(__nv_bfloat16*)(g_FtH + o) = h;
            *(__nv_bfloat16*)(g_FtL + o) = lo;
        }
    } else {
        int r = blk - (2 * DEPTH + 1);
        int i = r / B, b = r % B;
        int h = threadIdx.x;
        if (h < HID) {
            float acc = bfwd[i * HID + h] + bcode[i * HID + h];
            const float* wr = Wcode + ((long)i * HID + h) * CODEL;
            const float* av = a + (long)b * CODEL;
            #pragma unroll 4
            for (int c = 0; c < CODEL; c++) acc = fmaf(wr[c], av[c], acc);
            g_code[(i * B + b) * HID + h] = acc;
        }
    }
}

// ---------------- main kernel: 512 thr, 16 warps, 32pt x 32ch per warp ----------------
__global__ void __launch_bounds__(NTH, 1)
main_kernel(const float* __restrict__ x, const float* __restrict__ bftr,
            const float* __restrict__ Wout, const float* __restrict__ bout,
            float* __restrict__ out, int N, int B) {
    extern __shared__ __align__(1024) char sm[];
    float* code_sh = (float*)(sm + C_CODE);
    float* bftr_sh = (float*)(sm + C_BFTR);
    float* wout_sh = (float*)(sm + C_WOUT);
    float* outp    = (float*)(sm + C_Y);   // reused in final layer only

    const int t = threadIdx.x;
    const int warp = t >> 5, lane = t & 31;
    const int wm = warp & 3, wn = warp >> 2;
    const int chb = wn * 32;
    const uint32_t smb = smem_u32(sm);
    const long pt0 = (long)blockIdx.x * TILE;
    const int b = (int)(pt0 / N);

    // ---- group F01: filter stacks 0,1 -> slots 0,1 ----
    for (int j = t; j < 256; j += NTH) {
        cp16(smb + C_FH + j * 16, g_FtH + j * 16);
        cp16(smb + C_FL + j * 16, g_FtL + j * 16);
        cp16(smb + C_FH + 4096 + j * 16, g_FtH + 4096 + j * 16);
        cp16(smb + C_FL + 4096 + j * 16, g_FtL + 4096 + j * 16);
    }
    CP_COMMIT();
    // ---- S0/S1: W layer0 half0->buf0, half1->buf1 (each its own group) ----
    for (int hh = 0; hh < 2; hh++) {
        for (int j = t; j < 1024; j += NTH) {
            int n = j >> 3, q = j & 7;
            int goff = n * 256 + hh * 128 + q * 16;
            int soff = n * 128 + q * 16;
            cp16(smb + C_W + hh * 32768 + soff,         g_WfH[0] + goff);
            cp16(smb + C_W + hh * 32768 + 16384 + soff, g_WfL[0] + goff);
        }
        CP_COMMIT();
    }

    for (int idx = t; idx < DEPTH * HID; idx += NTH)
        code_sh[idx] = g_code[((idx >> 7) * B + b) * HID + (idx & 127)];
    for (int idx = t; idx < 6 * HID; idx += NTH) bftr_sh[idx] = bftr[idx];
    if (t < HID) wout_sh[t] = Wout[t];

    // ---- spherical harmonics: t<128 one point; rows 80B (conflict-free ldsm) ----
    if (t < TILE) {
        float Y[6][9];
        const float* xp = x + (pt0 + t) * 2;
        float theta = xp[0], phi = xp[1];
        float c = cosf(phi);
        float s2 = sqrtf(fmaxf(1.0f - c * c, 0.0f));
        float ct = cosf(theta), st = sinf(theta);
        float cmv = 1.0f, smv = 0.0f, pmm = 1.0f;
        #pragma unroll
        for (int m = 0; m <= 4; m++) {
            if (m > 0) {
                pmm *= -(2.0f * m - 1.0f) * s2;
                float cn = cmv * ct - smv * st;
                float sn = smv * ct + cmv * st;
                cmv = cn; smv = sn;
            }
            float Pm2 = pmm;
            float Pm1 = c * (2.0f * m + 1.0f) * pmm;
            #pragma unroll
            for (int s = 0; s <= 5; s++) {
                float P;
                if (s == 0)      P = Pm2;
                else if (s == 1) P = Pm1;
                else {
                    int l = m + s;
                    float Pl = ((2.0f * l - 1.0f) * c * Pm1 - (float)(l + m - 1) * Pm2) / (float)(l - m);
                    Pm2 = Pm1; Pm1 = Pl; P = Pl;
                }
                float base = g_norm[m][s] * P;
                if (m == 0) Y[s][4] = base;
                else { Y[s][4 + m] = base * cmv; Y[s][4 - m] = base * smv; }
            }
        }
        #pragma unroll
        for (int s = 0; s < 6; s++) {
            uint32_t* row = (uint32_t*)(sm + C_Y + (s * TILE + t) * 80);
            #pragma unroll
            for (int j = 0; j < 8; j++) {
                float a0 = (2 * j < 9) ? Y[s][2 * j] : 0.0f;
                float a1 = (2 * j + 1 < 9) ? Y[s][2 * j + 1] : 0.0f;
                __nv_bfloat16 h0 = __float2bfloat16_rn(a0), h1 = __float2bfloat16_rn(a1);
                row[j]     = pack_bf2(a0, a1);
                row[8 + j] = pack_bf2(a0 - __bfloat162float(h0), a1 - __bfloat162float(h1));
            }
        }
    }
    CP_WAIT2();        // F01 complete (S0,S1 may still be in flight)
    __syncthreads();

    const float bo = bout[0];
    float accD[8][4], accF[8][4];

    // per-lane fragment addressing (validated in rounds 3/6)
    const uint32_t rowloc = lane & 15;            // A-frag row within 16
    const uint32_t zsel   = lane >> 4;            // A-frag k8 select
    const uint32_t fbn    = (lane & 7) + ((lane >> 4) << 3);  // B-frag n within 16
    const uint32_t wk8    = (lane >> 3) & 1;      // B-frag k8 select
    const uint32_t erow   = lane >> 2;            // epilogue row within 8
    const int      ecol2  = 2 * (lane & 3);       // epilogue col pair
    uint32_t zr[2], n0v[2];
    #pragma unroll
    for (int mt = 0; mt < 2; mt++) zr[mt] = 32 * wm + 16 * mt + rowloc;
    #pragma unroll
    for (int np = 0; np < 2; np++) n0v[np] = (uint32_t)(chb + np * 16) + fbn;

    // ---- filter GEMM: accF = Y_st (x) Wftr_st + bftr_st ----
    auto filter_gemm = [&](int st, int sl) {
        #pragma unroll
        for (int mt = 0; mt < 2; mt++)
            #pragma unroll
            for (int nt = 0; nt < 4; nt++) {
                float v0 = bftr_sh[st * HID + chb + nt * 8 + ecol2];
                float v1 = bftr_sh[st * HID + chb + nt * 8 + ecol2 + 1];
                accF[mt * 4 + nt][0] = v0; accF[mt * 4 + nt][1] = v1;
                accF[mt * 4 + nt][2] = v0; accF[mt * 4 + nt][3] = v1;
            }
        uint32_t bH[2][4], bL[2][4];
        #pragma unroll
        for (int np = 0; np < 2; np++) {
            uint32_t boff = (uint32_t)sl * 4096 + n0v[np] * 32 + wk8 * 16;
            ldsm4(bH[np], smb + C_FH + boff);
            ldsm4(bL[np], smb + C_FL + boff);
        }
        #pragma unroll
        for (int mt = 0; mt < 2; mt++) {
            uint32_t ya = smb + C_Y + (uint32_t)st * 10240 + zr[mt] * 80 + zsel * 16;
            uint32_t aH[4], aL[4];
            ldsm4(aH, ya);
            ldsm4(aL, ya + 32);
            #pragma unroll
            for (int np = 0; np < 2; np++) {
                mma16816(accF[mt * 4 + 2 * np],     aH, bH[np][0], bH[np][1]);
                mma16816(accF[mt * 4 + 2 * np + 1], aH, bH[np][2], bH[np][3]);
                mma16816(accF[mt * 4 + 2 * np],     aH, bL[np][0], bL[np][1]);
                mma16816(accF[mt * 4 + 2 * np + 1], aH, bL[np][2], bL[np][3]);
                mma16816(accF[mt * 4 + 2 * np],     aL, bH[np][0], bH[np][1]);
                mma16816(accF[mt * 4 + 2 * np + 1], aL, bH[np][2], bH[np][3]);
            }
        }
    };

    // ---- z store: v[8][4] -> Z hi/lo planes (own rows, own channel group) ----
    auto store_z = [&](float (*v)[4]) {
        #pragma unroll
        for (int mt = 0; mt < 2; mt++)
            #pragma unroll
            for (int nt = 0; nt < 4; nt++) {
                uint32_t er0 = 32 * wm + 16 * mt + erow, er1 = er0 + 8;
                uint32_t kc = (uint32_t)(wn * 4 + nt);
                uint32_t a0 = er0 * 256 + ((kc ^ (er0 & 7)) << 4) + (lane & 3) * 4;
                uint32_t a1 = er1 * 256 + ((kc ^ (er1 & 7)) << 4) + (lane & 3) * 4;
                float z0 = v[mt * 4 + nt][0], z1 = v[mt * 4 + nt][1];
                float z2 = v[mt * 4 + nt][2], z3 = v[mt * 4 + nt][3];
                __nv_bfloat16 h0 = __float2bfloat16_rn(z0), h1 = __float2bfloat16_rn(z1);
                __nv_bfloat16 h2 = __float2bfloat16_rn(z2), h3 = __float2bfloat16_rn(z3);
                *(uint32_t*)(sm + C_ZH + a0) = pack_bf2(z0, z1);
                *(uint32_t*)(sm + C_ZH + a1) = pack_bf2(z2, z3);
                *(uint32_t*)(sm + C_ZL + a0) =
                    pack_bf2(z0 - __bfloat162float(h0), z1 - __bfloat162float(h1));
                *(uint32_t*)(sm + C_ZL + a1) =
                    pack_bf2(z2 - __bfloat162float(h2), z3 - __bfloat162float(h3));
            }
    };

    // ---- main GEMM K-half h (W from buf h): accD += z (x) Wfwd ----
    auto gemm_half = [&](int h) {
        uint32_t wbase = smb + C_W + (uint32_t)h * 32768;
        #pragma unroll
        for (int ks = 0; ks < 4; ks++) {
            int ksg = 4 * h + ks;
            uint32_t bH[2][4], bL[2][4];
            #pragma unroll
            for (int np = 0; np < 2; np++) {
                uint32_t boff = n0v[np] * 128 +
                    (((uint32_t)(2 * ks) + wk8) ^ (n0v[np] & 7)) * 16;
                ldsm4(bH[np], wbase + boff);
                ldsm4(bL[np], wbase + 16384 + boff);
            }
            #pragma unroll
            for (int mt = 0; mt < 2; mt++) {
                uint32_t aseg = (((uint32_t)(2 * ksg) + zsel) ^ (zr[mt] & 7)) << 4;
                uint32_t aH[4], aL[4];
                ldsm4(aH, smb + C_ZH + zr[mt] * 256 + aseg);
                ldsm4(aL, smb + C_ZL + zr[mt] * 256 + aseg);
                #pragma unroll
                for (int np = 0; np < 2; np++) {
                    mma16816(accD[mt * 4 + 2 * np],     aH, bH[np][0], bH[np][1]);
                    mma16816(accD[mt * 4 + 2 * np + 1], aH, bH[np][2], bH[np][3]);
                    mma16816(accD[mt * 4 + 2 * np],     aH, bL[np][0], bL[np][1]);
                    mma16816(accD[mt * 4 + 2 * np + 1], aH, bL[np][2], bL[np][3]);
                    mma16816(accD[mt * 4 + 2 * np],     aL, bH[np][0], bH[np][1]);
                    mma16816(accD[mt * 4 + 2 * np + 1], aL, bH[np][2], bH[np][3]);
                }
            }
        }
    };

    auto stage_w = [&](int li, int lh, int d) {
        const unsigned char* gh = g_WfH[li];
        const unsigned char* gl = g_WfL[li];
        for (int j = t; j < 1024; j += NTH) {
            int n = j >> 3, q = j & 7;
            int goff = n * 256 + lh * 128 + q * 16;
            int soff = n * 128 + q * 16;
            cp16(smb + C_W + d * 32768 + soff,         gh + goff);
            cp16(smb + C_W + d * 32768 + 16384 + soff, gl + goff);
        }
    };
    auto stage_f = [&](int st, int sl) {
        for (int j = t; j < 256; j += NTH) {
            cp16(smb + C_FH + sl * 4096 + j * 16, g_FtH + st * 4096 + j * 16);
            cp16(smb + C_FL + sl * 4096 + j * 16, g_FtL + st * 4096 + j * 16);
        }
    };

    // ---- z0 = filter(Y0) + bftr0 ----
    filter_gemm(0, 0);
    store_z(accF);

    // ---- layers (pipelined W halves: half0<-buf0, half1<-buf1) ----
    for (int i = 0; i < DEPTH; i++) {
        #pragma unroll
        for (int mt = 0; mt < 2; mt++)
            #pragma unroll
            for (int nt = 0; nt < 4; nt++) {
                float v0 = code_sh[i * HID + chb + nt * 8 + ecol2];
                float v1 = code_sh[i * HID + chb + nt * 8 + ecol2 + 1];
                accD[mt * 4 + nt][0] = v0; accD[mt * 4 + nt][1] = v1;
                accD[mt * 4 + nt][2] = v0; accD[mt * 4 + nt][3] = v1;
            }
        CP_WAIT1();            // half0 of layer i ready (half1 may be in flight)
        __syncthreads();       // + z stores of prev layer visible
        gemm_half(0);
        __syncthreads();       // all warps done with buf0 (and filter slot i&1)
        if (i < DEPTH - 1) {
            stage_w(i + 1, 0, 0);      // next layer half0 -> buf0
            stage_f(i + 2, i & 1);     // filter stack i+2 -> slot i&1
            CP_COMMIT();
        }
        if (i < DEPTH - 1) CP_WAIT1(); else CP_WAIT0();   // half1 ready
        __syncthreads();
        gemm_half(1);
        __syncthreads();       // all warps done with buf1 + old z reads done
        if (i < DEPTH - 1) {
            stage_w(i + 1, 1, 1);      // next layer half1 -> buf1
            CP_COMMIT();
        }
        filter_gemm(i + 1, (i + 1) & 1);
        if (i < DEPTH - 1) {
            float znew[8][4];
            #pragma unroll
            for (int q = 0; q < 8; q++) {
                znew[q][0] = accD[q][0] * accF[q][0];
                znew[q][1] = accD[q][1] * accF[q][1];
                znew[q][2] = accD[q][2] * accF[q][2];
                znew[q][3] = accD[q][3] * accF[q][3];
            }
            store_z(znew);
        } else {
            // final: out = ((D+code)*(F)) . Wout + bout
            #pragma unroll
            for (int mt = 0; mt < 2; mt++) {
                float p0 = 0.0f, p1 = 0.0f;
                #pragma unroll
                for (int nt = 0; nt < 4; nt++) {
                    int c0 = chb + nt * 8 + ecol2;
                    float w0 = wout_sh[c0], w1 = wout_sh[c0 + 1];
                    int id = mt * 4 + nt;
                    p0 = fmaf(accD[id][0] * accF[id][0], w0, p0);
                    p0 = fmaf(accD[id][1] * accF[id][1], w1, p0);
                    p1 = fmaf(accD[id][2] * accF[id][2], w0, p1);
                    p1 = fmaf(accD[id][3] * accF[id][3], w1, p1);
                }
                p0 += __shfl_xor_sync(0xffffffffu, p0, 1);
                p0 += __shfl_xor_sync(0xffffffffu, p0, 2);
                p1 += __shfl_xor_sync(0xffffffffu, p1, 1);
                p1 += __shfl_xor_sync(0xffffffffu, p1, 2);
                if ((lane & 3) == 0) {
                    outp[wn * TILE + 32 * wm + 16 * mt + erow]     = p0;
                    outp[wn * TILE + 32 * wm + 16 * mt + erow + 8] = p1;
                }
            }
            __syncthreads();
            if (t < TILE)
                out[pt0 + t] = outp[t] + outp[TILE + t] + outp[2 * TILE + t]
                             + outp[3 * TILE + t] + bo;
        }
    }
}

// ---------------------------------------------------------------------------
extern "C" void kernel_launch(void* const* d_in, const int* in_sizes, int n_in,
                              void* d_out, int out_size) {
    const float* x     = (const float*)d_in[0];
    const float* a     = (const float*)d_in[1];
    const float* Wftr  = (const float*)d_in[2];
    const float* bftr  = (const float*)d_in[3];
    const float* Wfwd  = (const float*)d_in[4];
    const float* bfwd  = (const float*)d_in[5];
    const float* Wcode = (const float*)d_in[6];
    const float* bcode = (const float*)d_in[7];
    const float* Wout  = (const float*)d_in[8];
    const float* bout  = (const float*)d_in[9];
    float* out = (float*)d_out;

    int  B  = in_sizes[1] / CODEL;
    long BN = (long)in_sizes[0] / 2;
    int  N  = (int)(BN / B);

    prep_all<<<2 * DEPTH + 1 + DEPTH * B, 128>>>(a, Wcode, bcode, bfwd, Wfwd, Wftr, B);

    cudaFuncSetAttribute(main_kernel, cudaFuncAttributeMaxDynamicSharedMemorySize, SMEM_SZ);
    int blocks = (int)(BN / TILE);
    main_kernel<<<blocks, NTH, SMEM_SZ>>>(x, bftr, Wout, bout, out, N, B);

    if ((long)out_size >= BN * 3) {
        cudaMemcpyAsync(out + BN, x, (size_t)BN * 2 * sizeof(float),
                        cudaMemcpyDeviceToDevice, 0);
    }
}